// round 5
// baseline (speedup 1.0000x reference)
#include <cuda_runtime.h>
#include <cstdint>

#define NP      32768
#define NB      128
#define NC      6
#define TOPK    400
#define KEEPK   200
#define NTH     1024
#define TILE    4096
#define EQCAP   4096
#define CONF_TH 0.5f
#define NMS_TH  0.5f
#define BIGF    1.0e9f
#define NEGF    (-1.0e9f)

// scratch keys: 128 * 32768 * 4B = 16 MB (static device array, no runtime alloc)
__device__ static unsigned int g_keys[(size_t)NB * NP];

__device__ __forceinline__ unsigned int fkey(float x) {
    unsigned int u = __float_as_uint(x);
    return (u & 0x80000000u) ? ~u : (u | 0x80000000u);
}
__device__ __forceinline__ float ikey(unsigned int k) {
    unsigned int u = (k & 0x80000000u) ? (k & 0x7fffffffu) : ~k;
    return __uint_as_float(u);
}

struct __align__(16) SmemT {
    union __align__(16) {
        float stage[TILE * 6];                                   // 96 KB (pass 0 staging)
        struct { unsigned int key[EQCAP]; unsigned int idx[EQCAP]; } eq;  // 32 KB
        unsigned int sup[TOPK * 16];                             // 25.6 KB (NMS bitmatrix)
    } u;
    unsigned int hist[4096];     // 16 KB
    unsigned int sscan[1024];    // 4 KB
    unsigned long long sortbuf[512];
    unsigned int selkey[512];
    unsigned int selidx[512];
    float4 cbox[TOPK];
    float  carea[TOPK];
    float  cscore[TOPK];
    float  clabel[TOPK];
    unsigned int keepw[16];
    int s_bin;
    int s_gt;
    unsigned int s_cnt;
    unsigned int s_eq;
};

// All 1024 threads. Finds largest bin d in [0,4096) with
// (count of keys in bins >= d) >= K; returns d and count of keys in bins > d.
__device__ void find_bin(SmemT& s, int K, int& bin_out, int& gt_out) {
    int t = threadIdx.x;
    unsigned int c[4];
    unsigned int sum = 0;
#pragma unroll
    for (int j = 0; j < 4; j++) { c[j] = s.hist[4 * t + j]; sum += c[j]; }
    s.sscan[t] = sum;
    if (t == 0) s.s_bin = -1;
    __syncthreads();
    for (int off = 1; off < 1024; off <<= 1) {
        unsigned int v = (t + off < 1024) ? s.sscan[t + off] : 0u;
        __syncthreads();
        s.sscan[t] += v;
        __syncthreads();
    }
    unsigned int after = s.sscan[t] - sum;  // sum over threads > t
    unsigned int run = after;
    int best = -1;
    unsigned int bestgt = 0;
#pragma unroll
    for (int j = 3; j >= 0; j--) {
        unsigned int cnt = c[j];
        if (best < 0 && run + cnt >= (unsigned int)K) { best = 4 * t + j; bestgt = run; }
        run += cnt;
    }
    if (best >= 0) atomicMax(&s.s_bin, best);
    __syncthreads();
    if (best >= 0 && best == s.s_bin) s.s_gt = (int)bestgt;
    __syncthreads();
    bin_out = s.s_bin;
    gt_out = s.s_gt;
}

__global__ __launch_bounds__(NTH, 1)
void box_selector_kernel(const float* __restrict__ pred,
                         const float* __restrict__ priors,
                         float* __restrict__ out) {
    extern __shared__ unsigned char smem_raw[];
    SmemT& s = *reinterpret_cast<SmemT*>(smem_raw);
    const int t = threadIdx.x;
    const int b = blockIdx.x;
    const float* pb = pred + (size_t)b * NP * NC;
    unsigned int* keys = g_keys + (size_t)b * NP;

    // ---------- pass 0: coalesced stream via smem staging, keys + 12-bit hist ----------
    for (int i = t; i < 4096; i += NTH) s.hist[i] = 0;
    __syncthreads();
    {
        const float4* srcbase = reinterpret_cast<const float4*>(pb);
        float4* stg4 = reinterpret_cast<float4*>(s.u.stage);
        for (int tile = 0; tile < NP / TILE; ++tile) {
            const float4* src = srcbase + tile * (TILE * 6 / 4);
#pragma unroll
            for (int j = 0; j < (TILE * 6 / 4) / NTH; ++j)       // 6 x LDG.128, coalesced
                stg4[t + j * NTH] = src[t + j * NTH];
            __syncthreads();
#pragma unroll
            for (int j = 0; j < TILE / NTH; ++j) {               // 4 rows / thread
                int r = t + j * NTH;
                float2 cf = *reinterpret_cast<const float2*>(s.u.stage + r * 6 + 4);
                float sc = fmaxf(cf.x, cf.y);
                float m = (sc > CONF_TH) ? sc : NEGF;
                unsigned int k = fkey(m);
                keys[tile * TILE + r] = k;
                unsigned int bin = k >> 20;
                unsigned int mm = __match_any_sync(0xffffffffu, bin);
                int leader = __ffs(mm) - 1;
                if ((t & 31) == leader) atomicAdd(&s.hist[bin], (unsigned int)__popc(mm));
            }
            __syncthreads();
        }
    }
    int d1, g1;
    find_bin(s, TOPK, d1, g1);
    int k1 = TOPK - g1;

    // ---------- merged scan: gather >d1 bins, compact ==d1 bin ----------
    if (t == 0) { s.s_cnt = 0; s.s_eq = 0; }
    __syncthreads();
    {
        const uint4* keys4 = reinterpret_cast<const uint4*>(keys);
        for (int n4 = t; n4 < NP / 4; n4 += NTH) {
            uint4 kv = keys4[n4];
            int base = n4 * 4;
            unsigned int kk[4] = {kv.x, kv.y, kv.z, kv.w};
#pragma unroll
            for (int l = 0; l < 4; ++l) {
                unsigned int k = kk[l];
                int top = (int)(k >> 20);
                if (top > d1) {
                    unsigned int p = atomicAdd(&s.s_cnt, 1u);
                    s.selkey[p] = k;
                    s.selidx[p] = (unsigned int)(base + l);
                } else if (top == d1) {
                    unsigned int e = atomicAdd(&s.s_eq, 1u);
                    if (e < EQCAP) { s.u.eq.key[e] = k; s.u.eq.idx[e] = (unsigned int)(base + l); }
                }
            }
        }
    }
    __syncthreads();
    int eqcnt = (int)s.s_eq;

    if (eqcnt <= EQCAP) {
        // in-smem exact ranking of pivot-bin entries (key desc, idx asc); take top k1
        for (int bb = 0; bb < eqcnt; bb += NTH) {
            int me = bb + t;
            bool act = me < eqcnt;
            unsigned int mk = 0, mi = 0;
            if (act) { mk = s.u.eq.key[me]; mi = s.u.eq.idx[me]; }
            int rank = 0;
            for (int j = 0; j < eqcnt; ++j) {
                unsigned int kj = s.u.eq.key[j];
                unsigned int ij = s.u.eq.idx[j];
                if (act && (kj > mk || (kj == mk && ij < mi))) rank++;
            }
            if (act && rank < k1) { s.selkey[g1 + rank] = mk; s.selidx[g1 + rank] = mi; }
        }
    } else {
        // ---------- fallback: radix refine within bin d1 (rare) ----------
        for (int i = t; i < 4096; i += NTH) s.hist[i] = 0;
        __syncthreads();
        for (int n = t; n < NP; n += NTH) {
            unsigned int k = keys[n];
            if ((int)(k >> 20) == d1) atomicAdd(&s.hist[(k >> 8) & 0xfffu], 1u);
        }
        __syncthreads();
        int d2, g2;
        find_bin(s, k1, d2, g2);
        int k2 = k1 - g2;
        unsigned int P24 = ((unsigned int)d1 << 12) | (unsigned int)d2;
        __syncthreads();
        for (int i = t; i < 4096; i += NTH) s.hist[i] = 0;
        __syncthreads();
        for (int n = t; n < NP; n += NTH) {
            unsigned int k = keys[n];
            if ((k >> 8) == P24) atomicAdd(&s.hist[k & 0xffu], 1u);
        }
        __syncthreads();
        int d3, g3;
        find_bin(s, k2, d3, g3);
        int need = k2 - g3;
        unsigned int KP = (P24 << 8) | (unsigned int)d3;
        if (t == 0) s.s_cnt = 0;
        __syncthreads();
        for (int n = t; n < NP; n += NTH) {
            unsigned int k = keys[n];
            if ((int)(k >> 20) == d1 && k > KP) {
                unsigned int p = atomicAdd(&s.s_cnt, 1u);
                s.selkey[g1 + p] = k;
                s.selidx[g1 + p] = (unsigned int)n;
            }
        }
        __syncthreads();
        if (t < 32) {   // equals: lowest `need` indices via ordered ballot
            int taken = 0;
            int slot0 = g1 + (k1 - need);
            for (int base2 = 0; base2 < NP && taken < need; base2 += 32) {
                unsigned int k = keys[base2 + t];
                bool e = (k == KP);
                unsigned int bal = __ballot_sync(0xffffffffu, e);
                int rank = __popc(bal & ((1u << t) - 1u));
                if (e && taken + rank < need) {
                    s.selkey[slot0 + taken + rank] = KP;
                    s.selidx[slot0 + taken + rank] = (unsigned int)(base2 + t);
                }
                taken += __popc(bal);
            }
        }
    }
    __syncthreads();

    // ---------- sort 1: descending (key, then lowest idx) -> exact top_k order ----------
    if (t < 512) {
        unsigned long long v = 0ull;
        if (t < TOPK)
            v = ((unsigned long long)s.selkey[t] << 32) | (unsigned int)(~s.selidx[t]);
        s.sortbuf[t] = v;
    }
    __syncthreads();
    for (int kk = 2; kk <= 512; kk <<= 1) {
        for (int j = kk >> 1; j > 0; j >>= 1) {
            if (t < 512) {
                int ixj = t ^ j;
                if (ixj > t) {
                    unsigned long long a = s.sortbuf[t], c = s.sortbuf[ixj];
                    bool desc = ((t & kk) == 0);
                    bool sw = desc ? (a < c) : (a > c);
                    if (sw) { s.sortbuf[t] = c; s.sortbuf[ixj] = a; }
                }
            }
            __syncthreads();
        }
    }

    // ---------- decode 400 candidates ----------
    if (t < 16) s.keepw[t] = (t == 12) ? 0xFFFF0000u : 0u;
    if (t < TOPK) {
        unsigned long long v = s.sortbuf[t];
        unsigned int k = (unsigned int)(v >> 32);
        unsigned int idx = ~(unsigned int)v;
        float sc = ikey(k);
        float4 pr = reinterpret_cast<const float4*>(priors)[idx];
        const float* pp = pb + (size_t)idx * 6;
        float l0 = pp[0], l1 = pp[1], l2 = pp[2], l3 = pp[3];
        float c0 = pp[4], c1 = pp[5];
        float cx = pr.x + l0 * 0.1f * pr.z;
        float cy = pr.y + l1 * 0.1f * pr.w;
        float w  = pr.z * expf(l2 * 0.2f);
        float h  = pr.w * expf(l3 * 0.2f);
        float4 bx = make_float4(cx - 0.5f * w, cy - 0.5f * h, cx + 0.5f * w, cy + 0.5f * h);
        s.cbox[t]   = bx;
        s.carea[t]  = (bx.z - bx.x) * (bx.w - bx.y);
        s.cscore[t] = sc;
        s.clabel[t] = (c1 > c0) ? 1.0f : 0.0f;
    }
    __syncthreads();
    if (t < TOPK) {
        if (!(s.cscore[t] > CONF_TH)) atomicOr(&s.keepw[t >> 5], 1u << (t & 31));
    }
    __syncthreads();

    // ---------- suppression bit matrix: sup[i][w] (j>i, iou>0.5) ----------
    for (int lin = t; lin < TOPK * 16; lin += NTH) {
        int i = lin >> 4;
        int w = lin & 15;
        unsigned int word = 0u;
        if (w < 13) {
            float4 bi = s.cbox[i];
            float ai = s.carea[i];
            int jbase = w * 32;
#pragma unroll 4
            for (int l = 0; l < 32; l++) {
                int j = jbase + l;
                if (j > i && j < TOPK) {
                    float4 bj = s.cbox[j];
                    float iw = fminf(bi.z, bj.z) - fmaxf(bi.x, bj.x);
                    float ih = fminf(bi.w, bj.w) - fmaxf(bi.y, bj.y);
                    iw = fmaxf(iw, 0.0f);
                    ih = fmaxf(ih, 0.0f);
                    float inter = iw * ih;
                    float iou = inter / (ai + s.carea[j] - inter + 1e-12f);
                    if (iou > NMS_TH) word |= (1u << l);
                }
            }
        }
        s.u.sup[lin] = word;
    }
    __syncthreads();

    // ---------- serial greedy NMS reduce ----------
    if (t == 0) {
        unsigned int r[13];
#pragma unroll
        for (int w = 0; w < 13; w++) r[w] = s.keepw[w];
        const uint4* sup4 = reinterpret_cast<const uint4*>(s.u.sup);
#pragma unroll
        for (int w = 0; w < 13; w++) {
#pragma unroll
            for (int bb = 0; bb < 32; bb++) {
                int i = w * 32 + bb;
                if (i >= TOPK) break;
                if (!((r[w] >> bb) & 1u)) {
                    uint4 a0 = sup4[i * 4 + 0];
                    uint4 a1 = sup4[i * 4 + 1];
                    uint4 a2 = sup4[i * 4 + 2];
                    uint4 a3 = sup4[i * 4 + 3];
                    r[0]  |= a0.x; r[1]  |= a0.y; r[2]  |= a0.z; r[3]  |= a0.w;
                    r[4]  |= a1.x; r[5]  |= a1.y; r[6]  |= a1.z; r[7]  |= a1.w;
                    r[8]  |= a2.x; r[9]  |= a2.y; r[10] |= a2.z; r[11] |= a2.w;
                    r[12] |= a3.x;
                }
            }
        }
#pragma unroll
        for (int w = 0; w < 13; w++) s.keepw[w] = r[w];
    }
    __syncthreads();

    // ---------- sort 2: ascending (keep ? score : BIG, then position) ----------
    if (t < 512) {
        unsigned long long v = 0xFFFFFFFFFFFFFFFFull;
        if (t < TOPK) {
            bool kp = !((s.keepw[t >> 5] >> (t & 31)) & 1u);
            float skf = kp ? s.cscore[t] : BIGF;
            unsigned int sk = __float_as_uint(skf);
            v = ((unsigned long long)sk << 32) | (unsigned int)t;
        }
        s.sortbuf[t] = v;
    }
    __syncthreads();
    for (int kk = 2; kk <= 512; kk <<= 1) {
        for (int j = kk >> 1; j > 0; j >>= 1) {
            if (t < 512) {
                int ixj = t ^ j;
                if (ixj > t) {
                    unsigned long long a = s.sortbuf[t], c = s.sortbuf[ixj];
                    bool asc = ((t & kk) == 0);
                    bool sw = asc ? (a > c) : (a < c);
                    if (sw) { s.sortbuf[t] = c; s.sortbuf[ixj] = a; }
                }
            }
            __syncthreads();
        }
    }

    // ---------- write output ----------
    if (t < KEEPK) {
        unsigned long long v = s.sortbuf[t];
        int c = (int)(unsigned int)(v & 0xffffffffu);
        bool kp = !((s.keepw[c >> 5] >> (c & 31)) & 1u);
        float* o = out + ((size_t)b * KEEPK + t) * 6;
        if (kp) {
            float4 bx = s.cbox[c];
            o[0] = s.clabel[c];
            o[1] = s.cscore[c];
            o[2] = bx.x; o[3] = bx.y; o[4] = bx.z; o[5] = bx.w;
        } else {
            o[0] = 0.0f; o[1] = 0.0f; o[2] = 0.0f;
            o[3] = 0.0f; o[4] = 0.0f; o[5] = 0.0f;
        }
    }
}

extern "C" void kernel_launch(void* const* d_in, const int* in_sizes, int n_in,
                              void* d_out, int out_size) {
    const float* pred = (const float*)d_in[0];
    const float* pri  = (const float*)d_in[1];
    if (n_in >= 2 && in_sizes[0] < in_sizes[1]) {
        const float* tmp = pred; pred = pri; pri = tmp;
    }
    float* out = (float*)d_out;
    cudaFuncSetAttribute(box_selector_kernel,
                         cudaFuncAttributeMaxDynamicSharedMemorySize,
                         (int)sizeof(SmemT));
    box_selector_kernel<<<NB, NTH, sizeof(SmemT)>>>(pred, pri, out);
}

// round 6
// speedup vs baseline: 1.5070x; 1.5070x over previous
#include <cuda_runtime.h>
#include <cstdint>

#define NP      32768
#define NB      128
#define NC      6
#define TOPK    400
#define KEEPK   200
#define NTH     1024
#define EQCAP   2048
#define CONF_TH 0.5f
#define NMS_TH  0.5f
#define BIGF    1.0e9f
#define NEGF    (-1.0e9f)

// scratch keys: 128 * 32768 * 4B = 16 MB (static device array, no runtime alloc)
__device__ static unsigned int g_keys[(size_t)NB * NP];

__device__ __forceinline__ unsigned int fkey(float x) {
    unsigned int u = __float_as_uint(x);
    return (u & 0x80000000u) ? ~u : (u | 0x80000000u);
}
__device__ __forceinline__ float ikey(unsigned int k) {
    unsigned int u = (k & 0x80000000u) ? (k & 0x7fffffffu) : ~k;
    return __uint_as_float(u);
}

struct __align__(16) SmemT {
    union __align__(16) {
        struct {
            unsigned int hist[4096];   // 16 KB
            unsigned int sscan[1024];  // 4 KB
        } sel;
        struct { unsigned int key[EQCAP]; unsigned int idx[EQCAP]; } eq;  // 16 KB
        unsigned int sup[TOPK * 16];   // 25.6 KB (13 words used, 16 padded)
    } u;
    unsigned long long sortbuf[512];   // 4 KB
    unsigned int selkey[512];
    unsigned int selidx[512];
    float2 p1[TOPK];                   // (x1,y1)
    float2 p2[TOPK];                   // (x2,y2)
    float  cscore[TOPK];
    float  clabel[TOPK];
    unsigned int keepw[16];
    int s_bin;
    int s_gt;
    unsigned int s_cnt;
    unsigned int s_eq;
};

// All 1024 threads. Finds largest bin d in [0,4096) with
// (count of keys in bins >= d) >= K; returns d and count of keys in bins > d.
__device__ void find_bin(SmemT& s, int K, int& bin_out, int& gt_out) {
    int t = threadIdx.x;
    unsigned int c[4];
    unsigned int sum = 0;
#pragma unroll
    for (int j = 0; j < 4; j++) { c[j] = s.u.sel.hist[4 * t + j]; sum += c[j]; }
    s.u.sel.sscan[t] = sum;
    if (t == 0) s.s_bin = -1;
    __syncthreads();
    for (int off = 1; off < 1024; off <<= 1) {
        unsigned int v = (t + off < 1024) ? s.u.sel.sscan[t + off] : 0u;
        __syncthreads();
        s.u.sel.sscan[t] += v;
        __syncthreads();
    }
    unsigned int after = s.u.sel.sscan[t] - sum;  // sum over threads > t
    unsigned int run = after;
    int best = -1;
    unsigned int bestgt = 0;
#pragma unroll
    for (int j = 3; j >= 0; j--) {
        unsigned int cnt = c[j];
        if (best < 0 && run + cnt >= (unsigned int)K) { best = 4 * t + j; bestgt = run; }
        run += cnt;
    }
    if (best >= 0) atomicMax(&s.s_bin, best);
    __syncthreads();
    if (best >= 0 && best == s.s_bin) s.s_gt = (int)bestgt;
    __syncthreads();
    bin_out = s.s_bin;
    gt_out = s.s_gt;
}

__global__ __launch_bounds__(NTH, 1)
void box_selector_kernel(const float* __restrict__ pred,
                         const float* __restrict__ priors,
                         float* __restrict__ out) {
    __shared__ SmemT s;
    const int t = threadIdx.x;
    const int b = blockIdx.x;
    const float* pb = pred + (size_t)b * NP * NC;
    unsigned int* keys = g_keys + (size_t)b * NP;

    // ---------- pass 0: keys + 12-bit histogram (direct loads; R4-style) ----------
    for (int i = t; i < 4096; i += NTH) s.u.sel.hist[i] = 0;
    __syncthreads();
    for (int n = t; n < NP; n += NTH) {
        float2 cf = *reinterpret_cast<const float2*>(pb + n * 6 + 4);
        float sc = fmaxf(cf.x, cf.y);
        float m = (sc > CONF_TH) ? sc : NEGF;
        unsigned int k = fkey(m);
        keys[n] = k;
        unsigned int bin = k >> 20;
        unsigned int mm = __match_any_sync(0xffffffffu, bin);
        int leader = __ffs(mm) - 1;
        if ((t & 31) == leader) atomicAdd(&s.u.sel.hist[bin], (unsigned int)__popc(mm));
    }
    __syncthreads();
    int d1, g1;
    find_bin(s, TOPK, d1, g1);
    int k1 = TOPK - g1;

    // ---------- merged scan: gather >d1 bins, compact ==d1 bin ----------
    if (t == 0) { s.s_cnt = 0; s.s_eq = 0; }
    __syncthreads();
    {
        const uint4* keys4 = reinterpret_cast<const uint4*>(keys);
        for (int n4 = t; n4 < NP / 4; n4 += NTH) {
            uint4 kv = keys4[n4];
            int base = n4 * 4;
            unsigned int kk[4] = {kv.x, kv.y, kv.z, kv.w};
#pragma unroll
            for (int l = 0; l < 4; ++l) {
                unsigned int k = kk[l];
                int top = (int)(k >> 20);
                if (top > d1) {
                    unsigned int p = atomicAdd(&s.s_cnt, 1u);
                    s.selkey[p] = k;
                    s.selidx[p] = (unsigned int)(base + l);
                } else if (top == d1) {
                    unsigned int e = atomicAdd(&s.s_eq, 1u);
                    if (e < EQCAP) { s.u.eq.key[e] = k; s.u.eq.idx[e] = (unsigned int)(base + l); }
                }
            }
        }
    }
    __syncthreads();
    int eqcnt = (int)s.s_eq;

    if (eqcnt <= EQCAP) {
        // exact ranking of pivot-bin entries (key desc, idx asc); take top k1
        for (int bb = 0; bb < eqcnt; bb += NTH) {
            int me = bb + t;
            bool act = me < eqcnt;
            unsigned int mk = 0, mi = 0;
            if (act) { mk = s.u.eq.key[me]; mi = s.u.eq.idx[me]; }
            int rank = 0;
            for (int j = 0; j < eqcnt; ++j) {
                unsigned int kj = s.u.eq.key[j];
                unsigned int ij = s.u.eq.idx[j];
                if (act && (kj > mk || (kj == mk && ij < mi))) rank++;
            }
            if (act && rank < k1) { s.selkey[g1 + rank] = mk; s.selidx[g1 + rank] = mi; }
        }
    } else {
        // ---------- fallback: radix refine within bin d1 (rare) ----------
        __syncthreads();
        for (int i = t; i < 4096; i += NTH) s.u.sel.hist[i] = 0;
        __syncthreads();
        for (int n = t; n < NP; n += NTH) {
            unsigned int k = keys[n];
            if ((int)(k >> 20) == d1) atomicAdd(&s.u.sel.hist[(k >> 8) & 0xfffu], 1u);
        }
        __syncthreads();
        int d2, g2;
        find_bin(s, k1, d2, g2);
        int k2 = k1 - g2;
        unsigned int P24 = ((unsigned int)d1 << 12) | (unsigned int)d2;
        __syncthreads();
        for (int i = t; i < 4096; i += NTH) s.u.sel.hist[i] = 0;
        __syncthreads();
        for (int n = t; n < NP; n += NTH) {
            unsigned int k = keys[n];
            if ((k >> 8) == P24) atomicAdd(&s.u.sel.hist[k & 0xffu], 1u);
        }
        __syncthreads();
        int d3, g3;
        find_bin(s, k2, d3, g3);
        int need = k2 - g3;
        unsigned int KP = (P24 << 8) | (unsigned int)d3;
        if (t == 0) s.s_cnt = 0;
        __syncthreads();
        for (int n = t; n < NP; n += NTH) {
            unsigned int k = keys[n];
            if ((int)(k >> 20) == d1 && k > KP) {
                unsigned int p = atomicAdd(&s.s_cnt, 1u);
                s.selkey[g1 + p] = k;
                s.selidx[g1 + p] = (unsigned int)n;
            }
        }
        __syncthreads();
        if (t < 32) {   // equals: lowest `need` indices via ordered ballot
            int taken = 0;
            int slot0 = g1 + (k1 - need);
            for (int base2 = 0; base2 < NP && taken < need; base2 += 32) {
                unsigned int k = keys[base2 + t];
                bool e = (k == KP);
                unsigned int bal = __ballot_sync(0xffffffffu, e);
                int rank = __popc(bal & ((1u << t) - 1u));
                if (e && taken + rank < need) {
                    s.selkey[slot0 + taken + rank] = KP;
                    s.selidx[slot0 + taken + rank] = (unsigned int)(base2 + t);
                }
                taken += __popc(bal);
            }
        }
    }
    __syncthreads();

    // ---------- sort 1: descending (key, then lowest idx) -> exact top_k order ----------
    if (t < 512) {
        unsigned long long v = 0ull;
        if (t < TOPK)
            v = ((unsigned long long)s.selkey[t] << 32) | (unsigned int)(~s.selidx[t]);
        s.sortbuf[t] = v;
    }
    __syncthreads();
    for (int kk = 2; kk <= 512; kk <<= 1) {
        for (int j = kk >> 1; j > 0; j >>= 1) {
            if (t < 512) {
                int ixj = t ^ j;
                if (ixj > t) {
                    unsigned long long a = s.sortbuf[t], c = s.sortbuf[ixj];
                    bool desc = ((t & kk) == 0);
                    bool sw = desc ? (a < c) : (a > c);
                    if (sw) { s.sortbuf[t] = c; s.sortbuf[ixj] = a; }
                }
            }
            __syncthreads();
        }
    }

    // ---------- decode 400 candidates (SoA) ----------
    if (t < 16) s.keepw[t] = (t == 12) ? 0xFFFF0000u : 0u;
    if (t < TOPK) {
        unsigned long long v = s.sortbuf[t];
        unsigned int k = (unsigned int)(v >> 32);
        unsigned int idx = ~(unsigned int)v;
        float sc = ikey(k);
        float4 pr = reinterpret_cast<const float4*>(priors)[idx];
        const float* pp = pb + (size_t)idx * 6;
        float l0 = pp[0], l1 = pp[1], l2 = pp[2], l3 = pp[3];
        float c0 = pp[4], c1 = pp[5];
        float cx = pr.x + l0 * 0.1f * pr.z;
        float cy = pr.y + l1 * 0.1f * pr.w;
        float w  = pr.z * expf(l2 * 0.2f);
        float h  = pr.w * expf(l3 * 0.2f);
        s.p1[t] = make_float2(cx - 0.5f * w, cy - 0.5f * h);
        s.p2[t] = make_float2(cx + 0.5f * w, cy + 0.5f * h);
        s.cscore[t] = sc;
        s.clabel[t] = (c1 > c0) ? 1.0f : 0.0f;
        if (!(sc > CONF_TH)) atomicOr(&s.keepw[t >> 5], 1u << (t & 31));
    }
    __syncthreads();

    // ---------- suppression bit matrix: warp-per-row, lane = j, conflict-free ----------
    {
        int wi = t >> 5;
        int lane = t & 31;
        for (int i = wi; i < TOPK; i += 32) {
            float2 a1 = s.p1[i];   // broadcast
            float2 a2 = s.p2[i];
            float ai = (a2.x - a1.x) * (a2.y - a1.y);
            int w0 = i >> 5;
            if (lane < w0) s.u.sup[i * 16 + lane] = 0u;   // empty lower-triangle words
            for (int word = w0; word < 13; ++word) {
                int j = (word << 5) | lane;
                bool supb = false;
                if (j > i && j < TOPK) {
                    float2 c1 = s.p1[j];
                    float2 c2 = s.p2[j];
                    float iw = fminf(a2.x, c2.x) - fmaxf(a1.x, c1.x);
                    float ih = fminf(a2.y, c2.y) - fmaxf(a1.y, c1.y);
                    iw = fmaxf(iw, 0.0f);
                    ih = fmaxf(ih, 0.0f);
                    float inter = iw * ih;
                    float aj = (c2.x - c1.x) * (c2.y - c1.y);
                    float iou = inter / (ai + aj - inter + 1e-12f);
                    supb = iou > NMS_TH;
                }
                unsigned int bal = __ballot_sync(0xffffffffu, supb);
                if (lane == 0) s.u.sup[i * 16 + word] = bal;
            }
        }
    }
    __syncthreads();

    // ---------- serial greedy NMS reduce (rolled inner loop: small I$ footprint) ----------
    if (t == 0) {
        unsigned int r[13];
#pragma unroll
        for (int w = 0; w < 13; w++) r[w] = s.keepw[w];
        const uint4* sup4 = reinterpret_cast<const uint4*>(s.u.sup);
#pragma unroll
        for (int w = 0; w < 13; w++) {
            int nbb = (w == 12) ? 16 : 32;   // rows 400..415 don't exist
#pragma unroll 1
            for (int bb = 0; bb < nbb; bb++) {
                int i = w * 32 + bb;
                if (!((r[w] >> bb) & 1u)) {
                    uint4 a0 = sup4[i * 4 + 0];
                    uint4 a1 = sup4[i * 4 + 1];
                    uint4 a2 = sup4[i * 4 + 2];
                    uint4 a3 = sup4[i * 4 + 3];
                    r[0]  |= a0.x; r[1]  |= a0.y; r[2]  |= a0.z; r[3]  |= a0.w;
                    r[4]  |= a1.x; r[5]  |= a1.y; r[6]  |= a1.z; r[7]  |= a1.w;
                    r[8]  |= a2.x; r[9]  |= a2.y; r[10] |= a2.z; r[11] |= a2.w;
                    r[12] |= a3.x;
                }
            }
        }
#pragma unroll
        for (int w = 0; w < 13; w++) s.keepw[w] = r[w];
    }
    __syncthreads();

    // ---------- sort 2: ascending (keep ? score : BIG, then position) ----------
    if (t < 512) {
        unsigned long long v = 0xFFFFFFFFFFFFFFFFull;
        if (t < TOPK) {
            bool kp = !((s.keepw[t >> 5] >> (t & 31)) & 1u);
            float skf = kp ? s.cscore[t] : BIGF;
            unsigned int sk = __float_as_uint(skf);
            v = ((unsigned long long)sk << 32) | (unsigned int)t;
        }
        s.sortbuf[t] = v;
    }
    __syncthreads();
    for (int kk = 2; kk <= 512; kk <<= 1) {
        for (int j = kk >> 1; j > 0; j >>= 1) {
            if (t < 512) {
                int ixj = t ^ j;
                if (ixj > t) {
                    unsigned long long a = s.sortbuf[t], c = s.sortbuf[ixj];
                    bool asc = ((t & kk) == 0);
                    bool sw = asc ? (a > c) : (a < c);
                    if (sw) { s.sortbuf[t] = c; s.sortbuf[ixj] = a; }
                }
            }
            __syncthreads();
        }
    }

    // ---------- write output ----------
    if (t < KEEPK) {
        unsigned long long v = s.sortbuf[t];
        int c = (int)(unsigned int)(v & 0xffffffffu);
        bool kp = !((s.keepw[c >> 5] >> (c & 31)) & 1u);
        float* o = out + ((size_t)b * KEEPK + t) * 6;
        if (kp) {
            float2 q1 = s.p1[c];
            float2 q2 = s.p2[c];
            o[0] = s.clabel[c];
            o[1] = s.cscore[c];
            o[2] = q1.x; o[3] = q1.y; o[4] = q2.x; o[5] = q2.y;
        } else {
            o[0] = 0.0f; o[1] = 0.0f; o[2] = 0.0f;
            o[3] = 0.0f; o[4] = 0.0f; o[5] = 0.0f;
        }
    }
}

extern "C" void kernel_launch(void* const* d_in, const int* in_sizes, int n_in,
                              void* d_out, int out_size) {
    const float* pred = (const float*)d_in[0];
    const float* pri  = (const float*)d_in[1];
    if (n_in >= 2 && in_sizes[0] < in_sizes[1]) {
        const float* tmp = pred; pred = pri; pri = tmp;
    }
    float* out = (float*)d_out;
    box_selector_kernel<<<NB, NTH>>>(pred, pri, out);
}